// round 3
// baseline (speedup 1.0000x reference)
#include <cuda_runtime.h>

// x: (2,8,4,256,384) fp32 -> 16 independent DxHxW volumes
#define WD   384
#define HT   256
#define DP   4
#define HW   (HT*WD)          // 98304
#define DHW  (DP*HW)          // 393216
#define NIMG 16

#define TX 32
#define TY 4
#define VX 4
#define TILE_W (TX*VX)        // 128
#define SH (TY+2)             // 6
#define SD (DP+2)             // 6
#define SW 136                // col 3 left halo, cols 4..131 data, col 132 right halo
#define COL0 4

#define NROWS (SD*SH)         // 36
#define SLOTS 34              // 32 float4 slots + 2 scalar halos per row
#define NITEMS (NROWS*SLOTS)  // 1224
#define NTHR (TX*TY)          // 128

#define BONUS 10.0f

__global__ __launch_bounds__(NTHR)
void cqi_kernel(const float* __restrict__ xg, float* __restrict__ out)
{
    __shared__ float tile[SD][SH][SW];

    const int img = blockIdx.z;
    const int w0  = blockIdx.x * TILE_W;
    const int h0  = blockIdx.y * TY;
    const int tid = threadIdx.y * TX + threadIdx.x;

    const float* __restrict__ xin = xg + (size_t)img * DHW;

    // ---- cooperative vectorized tile load with edge clamping ----
    #pragma unroll
    for (int it = 0; it < (NITEMS + NTHR - 1) / NTHR; ++it) {
        int idx = tid + it * NTHR;
        if (idx < NITEMS) {
            int rowid = idx / SLOTS;
            int slot  = idx - rowid * SLOTS;
            int p = rowid / SH;
            int r = rowid - p * SH;
            int gd = p - 1;      gd = gd < 0 ? 0 : (gd > DP-1 ? DP-1 : gd);
            int gh = h0 + r - 1; gh = gh < 0 ? 0 : (gh > HT-1 ? HT-1 : gh);
            const float* rowp = xin + gd * HW + gh * WD;
            if (slot < 32) {
                float4 q = *(const float4*)(rowp + w0 + 4 * slot);
                *(float4*)&tile[p][r][COL0 + 4 * slot] = q;
            } else if (slot == 32) {
                int gw = w0 - 1; if (gw < 0) gw = 0;
                tile[p][r][COL0 - 1] = rowp[gw];
            } else {
                int gw = w0 + TILE_W; if (gw > WD - 1) gw = WD - 1;
                tile[p][r][COL0 + TILE_W] = rowp[gw];
            }
        }
    }
    __syncthreads();

    const int tx = threadIdx.x, ty = threadIdx.y;
    const int wb = w0 + VX * tx;        // first output w of this thread
    const int h  = h0 + ty;
    const int cb = COL0 + VX * tx;      // smem col of first output point

    // rolling 3-plane register window: win[slot][row][col(-1..4)]
    float win[3][3][6];
    float vmx[3][6];                    // per-plane vertical (row) max per col

    #define LOAD_PLANE(P, S)                                                   \
        do {                                                                   \
            _Pragma("unroll")                                                  \
            for (int i = 0; i < 3; ++i) {                                      \
                float4 q = *(const float4*)&tile[(P)][ty + i][cb];             \
                float lft = tile[(P)][ty + i][cb - 1];                         \
                float rgt = tile[(P)][ty + i][cb + 4];                         \
                win[(S)][i][0] = lft;  win[(S)][i][1] = q.x;                   \
                win[(S)][i][2] = q.y;  win[(S)][i][3] = q.z;                   \
                win[(S)][i][4] = q.w;  win[(S)][i][5] = rgt;                   \
            }                                                                  \
            _Pragma("unroll")                                                  \
            for (int c = 0; c < 6; ++c)                                        \
                vmx[(S)][c] = fmaxf(fmaxf(win[(S)][0][c], win[(S)][1][c]),     \
                                    win[(S)][2][c]);                           \
        } while (0)

    LOAD_PLANE(0, 0);
    LOAD_PLANE(1, 1);

    float* __restrict__ oc0 = out + (size_t)img * 3 * DHW;
    float* __restrict__ oc1 = oc0 + DHW;
    float* __restrict__ oc2 = oc1 + DHW;
    float* __restrict__ oy  = out + (size_t)NIMG * 3 * DHW + (size_t)img * DHW;

    #pragma unroll
    for (int d = 0; d < DP; ++d) {
        const int sa = d % 3, sb = (d + 1) % 3, sc = (d + 2) % 3;
        LOAD_PLANE(d + 2, sc);

        // cross-plane column max (27-neighborhood vertical+depth folded)
        float colm[6];
        #pragma unroll
        for (int c = 0; c < 6; ++c)
            colm[c] = fmaxf(fmaxf(vmx[sa][c], vmx[sb][c]), vmx[sc][c]);

        float r0[VX], r1[VX], r2[VX], ry[VX];

        #pragma unroll
        for (int j = 0; j < VX; ++j) {
            const int c = j + 1;
            // A = depth d-1, B = depth d, C = depth d+1
            const float xc = win[sb][1][c];

            const float b0 = 0.5f * (win[sb][1][c+1] - win[sb][1][c-1]);   // dx
            const float b1 = 0.5f * (win[sb][2][c]   - win[sb][0][c]);     // dy
            const float b2 = 0.5f * (win[sa][1][c]   - win[sc][1][c]);     // ds (flipped)

            const float dxx = win[sb][1][c+1] - 2.0f*xc + win[sb][1][c-1];
            const float dyy = win[sb][2][c]   - 2.0f*xc + win[sb][0][c];
            const float dss = win[sc][1][c]   - 2.0f*xc + win[sa][1][c];
            const float dxy = 0.25f * ( win[sb][0][c-1] - win[sb][0][c+1]
                                      - win[sb][2][c-1] + win[sb][2][c+1]);
            const float dys = 0.25f * (-win[sa][0][c] + win[sa][2][c]
                                      + win[sc][0][c] - win[sc][2][c]);
            const float dxs = 0.25f * (-win[sa][1][c-1] + win[sa][1][c+1]
                                      + win[sc][1][c-1] - win[sc][1][c+1]);

            const float mx = fmaxf(fmaxf(colm[c-1], colm[c]), colm[c+1]);
            const bool nms = (xc == mx);

            const float c00 = dyy*dss - dys*dys;
            const float c01 = dxs*dys - dxy*dss;
            const float c02 = dxy*dys - dxs*dyy;
            const float c11 = dxx*dss - dxs*dxs;
            const float c12 = dxy*dxs - dxx*dys;
            const float c22 = dxx*dyy - dxy*dxy;
            const float det = dxx*c00 + dxy*c01 + dxs*c02;

            const bool ok = nms && (det != 0.0f);
            const float invdet = __fdividef(1.0f, (det == 0.0f) ? 1.0f : det);

            const float u0 = (c00*b0 + c01*b1 + c02*b2) * invdet;
            const float u1 = (c01*b0 + c11*b1 + c12*b2) * invdet;
            const float u2 = (c02*b0 + c12*b1 + c22*b2) * invdet;

            float d0 = ok ? -u0 : 0.0f;
            float d1 = ok ? -u1 : 0.0f;
            float d2 = ok ? -u2 : 0.0f;

            const bool small = fmaxf(fmaxf(fabsf(d0), fabsf(d1)), fabsf(d2)) <= 0.7f;
            d0 = small ? d0 : 0.0f;
            d1 = small ? d1 : 0.0f;
            d2 = small ? d2 : 0.0f;

            const float dE = 0.5f * (b0*d0 + b1*d1 + b2*d2);
            const float y  = xc + dE + (ok ? BONUS : 0.0f);

            r0[j] = (float)d + d2;        // depth coord
            r1[j] = (float)(wb + j) + d0; // x (width) coord
            r2[j] = (float)h + d1;        // y (height) coord
            ry[j] = y;
        }

        const int o = d * HW + h * WD + wb;
        *(float4*)(oc0 + o) = make_float4(r0[0], r0[1], r0[2], r0[3]);
        *(float4*)(oc1 + o) = make_float4(r1[0], r1[1], r1[2], r1[3]);
        *(float4*)(oc2 + o) = make_float4(r2[0], r2[1], r2[2], r2[3]);
        *(float4*)(oy  + o) = make_float4(ry[0], ry[1], ry[2], ry[3]);
    }
    #undef LOAD_PLANE
}

extern "C" void kernel_launch(void* const* d_in, const int* in_sizes, int n_in,
                              void* d_out, int out_size)
{
    const float* x = (const float*)d_in[0];
    float* out = (float*)d_out;
    dim3 block(TX, TY, 1);
    dim3 grid(WD / TILE_W, HT / TY, NIMG);
    cqi_kernel<<<grid, block>>>(x, out);
}

// round 4
// speedup vs baseline: 1.8587x; 1.8587x over previous
#include <cuda_runtime.h>

// x: (2,8,4,256,384) fp32 -> 16 independent DxHxW volumes
#define WD   384
#define HT   256
#define DP   4
#define HW   (HT*WD)          // 98304
#define DHW  (DP*HW)          // 393216
#define NIMG 16

#define OUTW   30             // output columns per warp strip (lanes 1..30)
#define NSTRIP 13             // ceil(384/30)
#define CH     8              // output rows per h-chunk
#define NCH    (HT/CH)        // 32
#define WPB    4              // warps per block
#define NTASK  (NSTRIP*NCH*NIMG)   // 6656 warps

#define BONUS 10.0f
#define FULL  0xffffffffu

__global__ __launch_bounds__(128, 5)
void cqi_kernel(const float* __restrict__ xg, float* __restrict__ out)
{
    const int gw   = blockIdx.x * WPB + (threadIdx.x >> 5);
    const int lane = threadIdx.x & 31;

    const int img   = gw / (NSTRIP * NCH);
    const int rem   = gw - img * (NSTRIP * NCH);
    const int strip = rem % NSTRIP;
    const int hc    = rem / NSTRIP;

    const int w0   = strip * OUTW;
    const int wout = w0 + lane - 1;                 // this lane's output w
    const bool active = (lane >= 1) && (lane <= 30) && (wout < WD);
    int wcol = wout; if (wcol < 0) wcol = 0; if (wcol > WD-1) wcol = WD-1;

    const int h0 = hc * CH;

    const float* __restrict__ xin = xg + (size_t)img * DHW + wcol;

    // rolling 3-row window, per plane p=0..3:
    float valU[4], lfU[4], rgU[4], wmU[4];   // row h-1
    float valM[4], lfM[4], rgM[4], wmM[4];   // row h
    float valD[4], lfD[4], rgD[4], wmD[4];   // row h+1
    float pend[4];                           // raw prefetch of next row

    // load 4 plane values of one (clamped) row into dst[4]
    #define LOADROW(HR, DST)                                             \
        do {                                                             \
            const float* _p = xin + (HR) * WD;                           \
            (DST)[0] = __ldg(_p);                                        \
            (DST)[1] = __ldg(_p + HW);                                   \
            (DST)[2] = __ldg(_p + 2*HW);                                 \
            (DST)[3] = __ldg(_p + 3*HW);                                 \
        } while (0)

    // from raw[4]: produce shifted copies + w-folded depth-triple max
    #define COMMIT(RAW, V, LF, RG, WM)                                   \
        do {                                                             \
            _Pragma("unroll")                                            \
            for (int p = 0; p < 4; ++p) {                                \
                float _v = (RAW)[p];                                     \
                (V)[p]  = _v;                                            \
                (LF)[p] = __shfl_up_sync(FULL, _v, 1);                   \
                (RG)[p] = __shfl_down_sync(FULL, _v, 1);                 \
            }                                                            \
            float _m01 = fmaxf((RAW)[0], (RAW)[1]);                      \
            float _m12 = fmaxf((RAW)[1], (RAW)[2]);                      \
            float _m23 = fmaxf((RAW)[2], (RAW)[3]);                      \
            float _t0 = _m01;                                            \
            float _t1 = fmaxf(_m01, (RAW)[2]);                           \
            float _t2 = fmaxf(_m12, (RAW)[3]);                           \
            float _t3 = _m23;                                            \
            (WM)[0] = fmaxf(fmaxf(__shfl_up_sync(FULL,_t0,1), _t0),      \
                            __shfl_down_sync(FULL,_t0,1));               \
            (WM)[1] = fmaxf(fmaxf(__shfl_up_sync(FULL,_t1,1), _t1),      \
                            __shfl_down_sync(FULL,_t1,1));               \
            (WM)[2] = fmaxf(fmaxf(__shfl_up_sync(FULL,_t2,1), _t2),      \
                            __shfl_down_sync(FULL,_t2,1));               \
            (WM)[3] = fmaxf(fmaxf(__shfl_up_sync(FULL,_t3,1), _t3),      \
                            __shfl_down_sync(FULL,_t3,1));               \
        } while (0)

    // ---- prologue: rows h0-1 and h0 ----
    {
        float ra[4], rb[4];
        int r_up = h0 - 1; if (r_up < 0) r_up = 0;
        LOADROW(r_up, ra);
        LOADROW(h0,  rb);
        COMMIT(ra, valU, lfU, rgU, wmU);
        COMMIT(rb, valM, lfM, rgM, wmM);
        int r_dn = h0 + 1; if (r_dn > HT-1) r_dn = HT-1;
        LOADROW(r_dn, pend);
    }

    float* __restrict__ oc0 = out + (size_t)img * 3 * DHW;
    float* __restrict__ oy  = out + (size_t)NIMG * 3 * DHW + (size_t)img * DHW;

    const int PA[4] = {0, 0, 1, 2};    // clamped plane d-1
    const int PC[4] = {1, 2, 3, 3};    // clamped plane d+1

    int obase = h0 * WD + wout;

    #pragma unroll 2
    for (int i = 0; i < CH; ++i) {
        const int h = h0 + i;

        // consume prefetch, issue next prefetch (row h+2, clamped)
        float tmp[4];
        #pragma unroll
        for (int p = 0; p < 4; ++p) tmp[p] = pend[p];
        int rn = h + 2; if (rn > HT-1) rn = HT-1;
        LOADROW(rn, pend);
        COMMIT(tmp, valD, lfD, rgD, wmD);

        float r0[DP], r1[DP], r2[DP], ry[DP];

        #pragma unroll
        for (int d = 0; d < DP; ++d) {
            const int pa = PA[d], pc = PC[d];
            const float xc = valM[d];

            const float b0 = 0.5f * (rgM[d] - lfM[d]);        // dx
            const float b1 = 0.5f * (valD[d] - valU[d]);      // dy
            const float b2 = 0.5f * (valM[pa] - valM[pc]);    // ds (flipped)

            const float dxx = rgM[d]   - 2.0f*xc + lfM[d];
            const float dyy = valD[d]  - 2.0f*xc + valU[d];
            const float dss = valM[pc] - 2.0f*xc + valM[pa];
            const float dxy = 0.25f * ( lfU[d] - rgU[d] - lfD[d] + rgD[d]);
            const float dys = 0.25f * (-valU[pa] + valD[pa] + valU[pc] - valD[pc]);
            const float dxs = 0.25f * (-lfM[pa] + rgM[pa] + lfM[pc] - rgM[pc]);

            const float mx = fmaxf(fmaxf(wmU[d], wmM[d]), wmD[d]);
            const bool nms = (xc == mx);

            const float c00 = dyy*dss - dys*dys;
            const float c01 = dxs*dys - dxy*dss;
            const float c02 = dxy*dys - dxs*dyy;
            const float c11 = dxx*dss - dxs*dxs;
            const float c12 = dxy*dxs - dxx*dys;
            const float c22 = dxx*dyy - dxy*dxy;
            const float det = dxx*c00 + dxy*c01 + dxs*c02;

            const bool ok = nms && (det != 0.0f);
            const float invdet = __fdividef(1.0f, (det == 0.0f) ? 1.0f : det);

            const float u0 = (c00*b0 + c01*b1 + c02*b2) * invdet;
            const float u1 = (c01*b0 + c11*b1 + c12*b2) * invdet;
            const float u2 = (c02*b0 + c12*b1 + c22*b2) * invdet;

            float d0 = ok ? -u0 : 0.0f;
            float d1 = ok ? -u1 : 0.0f;
            float d2 = ok ? -u2 : 0.0f;

            const bool small = fmaxf(fmaxf(fabsf(d0), fabsf(d1)), fabsf(d2)) <= 0.7f;
            d0 = small ? d0 : 0.0f;
            d1 = small ? d1 : 0.0f;
            d2 = small ? d2 : 0.0f;

            const float dE = 0.5f * (b0*d0 + b1*d1 + b2*d2);

            r0[d] = (float)d + d2;
            r1[d] = (float)wout + d0;
            r2[d] = (float)h + d1;
            ry[d] = xc + dE + (ok ? BONUS : 0.0f);
        }

        if (active) {
            #pragma unroll
            for (int d = 0; d < DP; ++d) {
                oc0[obase + d*HW + 0*DHW] = r0[d];
                oc0[obase + d*HW + 1*DHW] = r1[d];
                oc0[obase + d*HW + 2*DHW] = r2[d];
                oy [obase + d*HW]         = ry[d];
            }
        }
        obase += WD;

        // rotate rolling window: U <- M <- D
        #pragma unroll
        for (int p = 0; p < 4; ++p) {
            valU[p]=valM[p]; lfU[p]=lfM[p]; rgU[p]=rgM[p]; wmU[p]=wmM[p];
            valM[p]=valD[p]; lfM[p]=lfD[p]; rgM[p]=rgD[p]; wmM[p]=wmD[p];
        }
    }
    #undef LOADROW
    #undef COMMIT
}

extern "C" void kernel_launch(void* const* d_in, const int* in_sizes, int n_in,
                              void* d_out, int out_size)
{
    const float* x = (const float*)d_in[0];
    float* out = (float*)d_out;
    dim3 block(WPB * 32, 1, 1);
    dim3 grid(NTASK / WPB, 1, 1);
    cqi_kernel<<<grid, block>>>(x, out);
}